// round 16
// baseline (speedup 1.0000x reference)
#include <cuda_runtime.h>

#define NPRIMES 168
#define TPB 128
#define COLS 128
#define NQ 4                       // pipeline quarters
#define QCOLS (524288 / NQ)        // 131072 columns per quarter
#define QGRID (QCOLS / COLS)       // 1024 blocks per quarter kernel
#define TABN (NPRIMES * 1000)

// Interleaved (kernel, bias) table: one LDG.64 fetches both values.
__device__ float2 g_tab[TABN];
// Per-column (w, b) staging buffer: gather_k writes, stream_k reads.
__device__ float2 g_wb[524288];

// Per-prime magic-mod descriptor (compile-time, constant memory):
//  magic = floor(2^32/p)+1  ->  k % p == k - p*umulhi(k, magic)   (k < 2^20)
struct PInfo { unsigned magic; int p; };

#define PRIME_LIST \
 X(2) X(3) X(5) X(7) X(11) X(13) X(17) X(19) X(23) X(29) \
 X(31) X(37) X(41) X(43) X(47) X(53) X(59) X(61) X(67) X(71) \
 X(73) X(79) X(83) X(89) X(97) X(101) X(103) X(107) X(109) X(113) \
 X(127) X(131) X(137) X(139) X(149) X(151) X(157) X(163) X(167) X(173) \
 X(179) X(181) X(191) X(193) X(197) X(199) X(211) X(223) X(227) X(229) \
 X(233) X(239) X(241) X(251) X(257) X(263) X(269) X(271) X(277) X(281) \
 X(283) X(293) X(307) X(311) X(313) X(317) X(331) X(337) X(347) X(349) \
 X(353) X(359) X(367) X(373) X(379) X(383) X(389) X(397) X(401) X(409) \
 X(419) X(421) X(431) X(433) X(439) X(443) X(449) X(457) X(461) X(463) \
 X(467) X(479) X(487) X(491) X(499) X(503) X(509) X(521) X(523) X(541) \
 X(547) X(557) X(563) X(569) X(571) X(577) X(587) X(593) X(599) X(601) \
 X(607) X(613) X(617) X(619) X(631) X(641) X(643) X(647) X(653) X(659) \
 X(661) X(673) X(677) X(683) X(691) X(701) X(709) X(719) X(727) X(733) \
 X(739) X(743) X(751) X(757) X(761) X(769) X(773) X(787) X(797) X(809) \
 X(811) X(821) X(823) X(827) X(829) X(839) X(853) X(857) X(859) X(863) \
 X(877) X(881) X(883) X(887) X(907) X(911) X(919) X(929) X(937) X(941) \
 X(947) X(953) X(967) X(971) X(977) X(983) X(991) X(997)

__constant__ PInfo C_PI[NPRIMES] = {
#define X(p) { 0xFFFFFFFFu / (unsigned)(p) + 1u, (p) },
  PRIME_LIST
#undef X
};

__global__ __launch_bounds__(256)
void interleave_tab(const float* __restrict__ kern, const float* __restrict__ bias)
{
    int i = blockIdx.x * 256 + threadIdx.x;
    if (i < TABN) g_tab[i] = make_float2(kern[i], bias[i]);
}

// ---- gather kernel: all warps gather (R7's proven loop), write g_wb ----
__global__ __launch_bounds__(TPB, 16)
void gather_k(int qoff)
{
    const int t = threadIdx.x;
    const unsigned k = (unsigned)(qoff + blockIdx.x * COLS + t);

    float w = 0.f, a = 0.f;
    const float2* __restrict__ row = g_tab;

#pragma unroll 8
    for (int i = 0; i < NPRIMES; ++i) {
        const PInfo pi = C_PI[i];
        int m = (int)(k - (unsigned)pi.p * __umulhi(k, pi.magic));   // k % p
        float2 e = __ldg(row + m);
        w += e.x; a += e.y;
        row += 1000;
    }
    g_wb[k] = make_float2(w, a);        // coalesced float2 store
}

// ---- stream kernel: pure DRAM streamer (R7's proven phase B) ----
__global__ __launch_bounds__(TPB, 16)
void stream_k(const float* __restrict__ x,
              float* __restrict__ out,
              int qoff, int N, int B)
{
    const int t    = threadIdx.x;
    const int k0   = qoff + blockIdx.x * COLS;
    const int col4 = t & 31;
    const int rpg  = B >> 2;            // 16
    const int rbeg = (t >> 5) * rpg;

    // per-thread (w,b) for its 4 columns: 2 coalesced float4 loads (L2-hot)
    const float4* wb4 = reinterpret_cast<const float4*>(g_wb + k0 + col4 * 4);
    const float4 p0 = __ldg(wb4);       // (w0,b0,w1,b1)
    const float4 p1 = __ldg(wb4 + 1);   // (w2,b2,w3,b3)
    const float4 wv = make_float4(p0.x, p0.z, p1.x, p1.z);
    const float4 bv = make_float4(p0.y, p0.w, p1.y, p1.w);

    const size_t nv = (size_t)(N >> 2);
    const float4* __restrict__ xv = reinterpret_cast<const float4*>(x)
                                    + (size_t)rbeg * nv + (k0 >> 2) + col4;
    float4* __restrict__       ov = reinterpret_cast<float4*>(out)
                                    + (size_t)rbeg * nv + (k0 >> 2) + col4;

#pragma unroll 8
    for (int r = 0; r < rpg; ++r) {
        float4 xi = __ldcs(xv);
        float4 o;
        o.x = fmaf(xi.x, wv.x, bv.x);
        o.y = fmaf(xi.y, wv.y, bv.y);
        o.z = fmaf(xi.z, wv.z, bv.z);
        o.w = fmaf(xi.w, wv.w, bv.w);
        __stcs(ov, o);
        xv += nv;
        ov += nv;
    }
}

extern "C" void kernel_launch(void* const* d_in, const int* in_sizes, int n_in,
                              void* d_out, int out_size)
{
    const float* x  = (const float*)d_in[0];   // (B, N) float32
    const float* kr = (const float*)d_in[1];   // (168, 1000) float32
    const float* br = (const float*)d_in[2];   // (168, 1000) float32
    float* out = (float*)d_out;

    const int N = 524288;
    const int B = in_sizes[0] / N;             // 64

    // Persistent side stream + events (created once; no device memory).
    static cudaStream_t s1 = nullptr;
    static cudaEvent_t  evG[NQ];
    static cudaEvent_t  evJoin = nullptr;
    if (s1 == nullptr) {
        cudaStreamCreateWithFlags(&s1, cudaStreamNonBlocking);
        for (int q = 0; q < NQ; ++q)
            cudaEventCreateWithFlags(&evG[q], cudaEventDisableTiming);
        cudaEventCreateWithFlags(&evJoin, cudaEventDisableTiming);
    }

    interleave_tab<<<(TABN + 255) / 256, 256>>>(kr, br);

    // Pipeline: gathers on the main stream, streams on s1 (fork via events).
    for (int q = 0; q < NQ; ++q) {
        gather_k<<<QGRID, TPB>>>(q * QCOLS);
        cudaEventRecord(evG[q], 0);
        cudaStreamWaitEvent(s1, evG[q], 0);
        stream_k<<<QGRID, TPB, 0, s1>>>(x, out, q * QCOLS, N, B);
    }

    // Join s1 back into the main stream before returning.
    cudaEventRecord(evJoin, s1);
    cudaStreamWaitEvent(0, evJoin, 0);
}

// round 17
// speedup vs baseline: 1.1005x; 1.1005x over previous
#include <cuda_runtime.h>

#define NPRIMES 168
#define TPB 128
#define COLS 128          // 1 column per thread
#define NBLK 4096         // N / COLS
#define TABN (NPRIMES * 1000)

// Interleaved (kernel, bias) table: one LDG.64 fetches both values.
__device__ float2 g_tab[TABN];
__device__ float  g_sink;   // un-DCE sink for warm kernel

// Per-prime magic-mod descriptor (compile-time, constant memory):
//  magic = floor(2^32/p)+1  ->  k % p == k - p*umulhi(k, magic)   (k < 2^20)
struct PInfo { unsigned magic; int p; };

#define PRIME_LIST \
 X(2) X(3) X(5) X(7) X(11) X(13) X(17) X(19) X(23) X(29) \
 X(31) X(37) X(41) X(43) X(47) X(53) X(59) X(61) X(67) X(71) \
 X(73) X(79) X(83) X(89) X(97) X(101) X(103) X(107) X(109) X(113) \
 X(127) X(131) X(137) X(139) X(149) X(151) X(157) X(163) X(167) X(173) \
 X(179) X(181) X(191) X(193) X(197) X(199) X(211) X(223) X(227) X(229) \
 X(233) X(239) X(241) X(251) X(257) X(263) X(269) X(271) X(277) X(281) \
 X(283) X(293) X(307) X(311) X(313) X(317) X(331) X(337) X(347) X(349) \
 X(353) X(359) X(367) X(373) X(379) X(383) X(389) X(397) X(401) X(409) \
 X(419) X(421) X(431) X(433) X(439) X(443) X(449) X(457) X(461) X(463) \
 X(467) X(479) X(487) X(491) X(499) X(503) X(509) X(521) X(523) X(541) \
 X(547) X(557) X(563) X(569) X(571) X(577) X(587) X(593) X(599) X(601) \
 X(607) X(613) X(617) X(619) X(631) X(641) X(643) X(647) X(653) X(659) \
 X(661) X(673) X(677) X(683) X(691) X(701) X(709) X(719) X(727) X(733) \
 X(739) X(743) X(751) X(757) X(761) X(769) X(773) X(787) X(797) X(809) \
 X(811) X(821) X(823) X(827) X(829) X(839) X(853) X(857) X(859) X(863) \
 X(877) X(881) X(883) X(887) X(907) X(911) X(919) X(929) X(937) X(941) \
 X(947) X(953) X(967) X(971) X(977) X(983) X(991) X(997)

__constant__ PInfo C_PI[NPRIMES] = {
#define X(p) { 0xFFFFFFFFu / (unsigned)(p) + 1u, (p) },
  PRIME_LIST
#undef X
};

__global__ __launch_bounds__(256)
void interleave_tab(const float* __restrict__ kern, const float* __restrict__ bias)
{
    int i = blockIdx.x * 256 + threadIdx.x;
    if (i < TABN) g_tab[i] = make_float2(kern[i], bias[i]);
}

// Warm x into L2 in the exact column-block order the streamers consume.
// Pure DRAM reads with high MLP; nearly zero issue-slot footprint.
__global__ __launch_bounds__(TPB, 16)
void warm_x(const float* __restrict__ x, int N)
{
    const int t    = threadIdx.x;
    const int col4 = t & 31;
    const int rbeg = (t >> 5) * 16;
    const size_t nv = (size_t)(N >> 2);

    float acc = 0.f;
    for (int cb = blockIdx.x; cb < NBLK; cb += gridDim.x) {
        const float4* __restrict__ xv = reinterpret_cast<const float4*>(x)
                                        + (size_t)rbeg * nv + (size_t)cb * 32 + col4;
#pragma unroll 8
        for (int r = 0; r < 16; ++r) {
            float4 v = __ldcg(xv);          // allocate in L2
            acc += v.x + v.y + v.z + v.w;
            xv += nv;
        }
    }
    if (__float_as_uint(acc) == 0x7f800001u)  // never true for finite data
        g_sink = acc;
}

// ---- main kernel: EXACTLY R7 (proven 65.5us) ----
__global__ __launch_bounds__(TPB, 16)
void bwl_prime_main(const float* __restrict__ x,
                    float* __restrict__ out,
                    int N, int B)
{
    __shared__ float w_s[COLS];
    __shared__ float b_s[COLS];

    const int t  = threadIdx.x;
    const int k0 = blockIdx.x * COLS;
    const unsigned k = (unsigned)(k0 + t);

    float w = 0.f, a = 0.f;
    const float2* __restrict__ row = g_tab;

#pragma unroll 8
    for (int i = 0; i < NPRIMES; ++i) {
        const PInfo pi = C_PI[i];
        int m = (int)(k - (unsigned)pi.p * __umulhi(k, pi.magic));  // k % p
        float2 e = __ldg(row + m);
        w += e.x; a += e.y;
        row += 1000;
    }

    w_s[t] = w;  b_s[t] = a;
    __syncthreads();

    const int col4 = t & 31;
    const int rpg  = B >> 2;
    const int rbeg = (t >> 5) * rpg;

    const float4 wv = *reinterpret_cast<const float4*>(&w_s[col4 * 4]);
    const float4 bv = *reinterpret_cast<const float4*>(&b_s[col4 * 4]);

    const size_t nv = (size_t)(N >> 2);
    const float4* __restrict__ xv = reinterpret_cast<const float4*>(x)
                                    + (size_t)rbeg * nv + (k0 >> 2) + col4;
    float4* __restrict__       ov = reinterpret_cast<float4*>(out)
                                    + (size_t)rbeg * nv + (k0 >> 2) + col4;

#pragma unroll 8
    for (int r = 0; r < rpg; ++r) {
        float4 xi = __ldcs(xv);
        float4 o;
        o.x = fmaf(xi.x, wv.x, bv.x);
        o.y = fmaf(xi.y, wv.y, bv.y);
        o.z = fmaf(xi.z, wv.z, bv.z);
        o.w = fmaf(xi.w, wv.w, bv.w);
        __stcs(ov, o);
        xv += nv;
        ov += nv;
    }
}

extern "C" void kernel_launch(void* const* d_in, const int* in_sizes, int n_in,
                              void* d_out, int out_size)
{
    const float* x  = (const float*)d_in[0];   // (B, N) float32
    const float* kr = (const float*)d_in[1];   // (168, 1000) float32
    const float* br = (const float*)d_in[2];   // (168, 1000) float32
    float* out = (float*)d_out;

    const int N = 524288;
    const int B = in_sizes[0] / N;             // 64

    // Persistent side stream + fork/join events (created once; no dev mem).
    static cudaStream_t s1 = nullptr;
    static cudaEvent_t  evFork = nullptr, evJoin = nullptr;
    if (s1 == nullptr) {
        cudaStreamCreateWithFlags(&s1, cudaStreamNonBlocking);
        cudaEventCreateWithFlags(&evFork, cudaEventDisableTiming);
        cudaEventCreateWithFlags(&evJoin, cudaEventDisableTiming);
    }

    // Fork: warm_x runs concurrently with interleave + main's gather phase.
    cudaEventRecord(evFork, 0);
    cudaStreamWaitEvent(s1, evFork, 0);
    warm_x<<<512, TPB, 0, s1>>>(x, N);
    cudaEventRecord(evJoin, s1);

    interleave_tab<<<(TABN + 255) / 256, 256>>>(kr, br);
    bwl_prime_main<<<NBLK, TPB>>>(x, out, N, B);

    // Join s1 back into the main stream before returning.
    cudaStreamWaitEvent(0, evJoin, 0);
}